// round 12
// baseline (speedup 1.0000x reference)
#include <cuda_runtime.h>
#include <cuda_bf16.h>

#define N_NODES 50000
#define N_EDGES 800000
#define NHID 128
#define BN_EPS 1e-5f
#define NBLK 196                 // ceil(50000/256)
#define NTILE 391                // ceil(50000/128)

typedef unsigned long long u64;
typedef unsigned int u32;

// ---------------- helpers ----------------------------------------------------
__device__ __forceinline__ u32 smem_u32(const void* p) {
    u32 a;
    asm("{ .reg .u64 t; cvta.to.shared.u64 t, %1; cvt.u32.u64 %0, t; }"
        : "=r"(a) : "l"(p));
    return a;
}
__device__ __forceinline__ void sts2f(u32 addr, float a, float b) {
    asm volatile("st.shared.v2.f32 [%0], {%1, %2};" :: "r"(addr), "f"(a), "f"(b) : "memory");
}
__device__ __forceinline__ void mma16816(float* c, u32 a0, u32 a1, u32 a2, u32 a3,
                                         u32 b0, u32 b1) {
    asm volatile(
        "mma.sync.aligned.m16n8k16.row.col.f32.bf16.bf16.f32 "
        "{%0,%1,%2,%3}, {%4,%5,%6,%7}, {%8,%9}, {%0,%1,%2,%3};"
        : "+f"(c[0]), "+f"(c[1]), "+f"(c[2]), "+f"(c[3])
        : "r"(a0), "r"(a1), "r"(a2), "r"(a3), "r"(b0), "r"(b1));
}
// split float4 -> {hi01, lo01, hi23, lo23} (bf16x2 words)
__device__ __forceinline__ uint4 split4i(float4 v) {
    __nv_bfloat162 h0 = __float22bfloat162_rn(make_float2(v.x, v.y));
    __nv_bfloat162 h1 = __float22bfloat162_rn(make_float2(v.z, v.w));
    float2 r0 = make_float2(v.x - __bfloat162float(h0.x), v.y - __bfloat162float(h0.y));
    float2 r1 = make_float2(v.z - __bfloat162float(h1.x), v.w - __bfloat162float(h1.y));
    __nv_bfloat162 l0 = __float22bfloat162_rn(r0);
    __nv_bfloat162 l1 = __float22bfloat162_rn(r1);
    uint4 q;
    q.x = *(u32*)&h0; q.y = *(u32*)&l0;
    q.z = *(u32*)&h1; q.w = *(u32*)&l1;
    return q;
}

// Fragment-major A layout (per 128-row tile, 8192 u64 = 64KB):
//   row r, u64-slot s (s = k-pair, 0..63; hi|lo packed per slot):
//   rb=r>>4, rr=r&15, ks=s>>3, s8=s&7
//   p  = (rr>=8) + 2*(s8>=4)        (fragment piece a0..a3)
//   fl = (rr&7)*4 + (s8&3)          (lane)
//   u64 idx = rb*1024 + ks*128 + fl*4 + p
// Warp load: uint4 @ u64(rbk*1024+ks*128+lane*4) = {a0h,a0l,a1h,a1l}, +1 -> {a2..}
//
// Fragment-major W layout (8192 u64 = 64KB):
//   col n, slot s: cb=n>>3, cc=n&7, p=(s8>=4), fl=cc*4+(s8&3)
//   u64 idx = cb*512 + ks*64 + fl*2 + p
// Warp load: uint4 @ u64(cbk*512+ks*64+lane*2) = {b0h,b0l,b1h,b1l}

// ---------------- scratch ----------------------------------------------------
__device__ float g_sum[NHID];
__device__ float g_sumsq[NHID];
__device__ float g_c2[NHID];
__device__ int   g_count[N_NODES];
__device__ int   g_off[N_NODES + 1];
__device__ int   g_cursor[N_NODES];
__device__ int   g_srcsorted[N_EDGES];
__device__ int   g_bsum[NBLK];
__device__ __align__(16) unsigned char g_Af[(size_t)NTILE * 65536];   // A frags
__device__ __align__(16) unsigned char g_Hf[(size_t)NTILE * 65536];   // H frags
__device__ __align__(16) unsigned char g_W1f[65536];
__device__ __align__(16) unsigned char g_W2f[65536];

// ---------------- front-end kernels (R8, measured-good) -----------------------
__global__ __launch_bounds__(256) void hist_kernel(const int* __restrict__ ei) {
    const int n8 = N_EDGES / 8;
    int idx = blockIdx.x * blockDim.x + threadIdx.x;
    if (idx >= n8) return;
    const int4* d4 = (const int4*)(ei + N_EDGES);
    int4 a = d4[idx];
    int4 b = d4[idx + n8];
    atomicAdd(&g_count[a.x], 1); atomicAdd(&g_count[a.y], 1);
    atomicAdd(&g_count[a.z], 1); atomicAdd(&g_count[a.w], 1);
    atomicAdd(&g_count[b.x], 1); atomicAdd(&g_count[b.y], 1);
    atomicAdd(&g_count[b.z], 1); atomicAdd(&g_count[b.w], 1);
}

__global__ __launch_bounds__(256) void partial_kernel() {
    int t = threadIdx.x;
    int i = blockIdx.x * 256 + t;
    int v = (i < N_NODES) ? g_count[i] : 0;
#pragma unroll
    for (int o = 16; o > 0; o >>= 1) v += __shfl_down_sync(~0u, v, o);
    __shared__ int ws[8];
    if ((t & 31) == 0) ws[t >> 5] = v;
    __syncthreads();
    if (t == 0) {
        int s = 0;
#pragma unroll
        for (int k = 0; k < 8; k++) s += ws[k];
        g_bsum[blockIdx.x] = s;
    }
}

__global__ __launch_bounds__(256) void offsets_kernel(const float* __restrict__ W1) {
    int t = threadIdx.x;
    int bid = blockIdx.x;
    if (bid == NBLK) {           // W1 -> fragment-major bf16 hi/lo
        if (t < 128) {
            const float4* wr = (const float4*)(W1 + t * NHID);
            uint2* o = (uint2*)g_W1f;
            int cb = t >> 3, cc = t & 7;
#pragma unroll 8
            for (int k4 = 0; k4 < 32; k4++) {
                uint4 q = split4i(wr[k4]);
                int s0 = 2 * k4, ks = s0 >> 3, s8 = s0 & 7;
                int p = (s8 >= 4) ? 1 : 0;
                int fl = cc * 4 + (s8 & 3);
                int i0 = cb * 512 + ks * 64 + fl * 2 + p;
                o[i0] = make_uint2(q.x, q.y);
                o[i0 + 2] = make_uint2(q.z, q.w);
            }
        }
        return;
    }
    __shared__ int sb[256];
    __shared__ int sh[256];
    sb[t] = (t < NBLK) ? g_bsum[t] : 0;
    __syncthreads();
#pragma unroll
    for (int o = 1; o < 256; o <<= 1) {
        int u = (t >= o) ? sb[t - o] : 0;
        __syncthreads();
        sb[t] += u;
        __syncthreads();
    }
    int base = (bid > 0) ? sb[bid - 1] : 0;

    int i = bid * 256 + t;
    int v = (i < N_NODES) ? g_count[i] : 0;
    sh[t] = v;
    __syncthreads();
#pragma unroll
    for (int o = 1; o < 256; o <<= 1) {
        int u = (t >= o) ? sh[t - o] : 0;
        __syncthreads();
        sh[t] += u;
        __syncthreads();
    }
    int off = base + sh[t] - v;
    if (i < N_NODES) {
        g_off[i] = off;
        g_cursor[i] = off;
        g_count[i] = 0;
    } else if (i == N_NODES) {
        g_off[N_NODES] = N_EDGES;
    }
    if (bid == 0 && t < NHID) { g_sum[t] = 0.f; g_sumsq[t] = 0.f; }
}

__global__ __launch_bounds__(256) void reorder_kernel(const int* __restrict__ ei) {
    const int n8 = N_EDGES / 8;
    int idx = blockIdx.x * blockDim.x + threadIdx.x;
    if (idx >= n8) return;
    const int4* s4 = (const int4*)ei;
    const int4* d4 = (const int4*)(ei + N_EDGES);
    int4 sa = s4[idx], sb = s4[idx + n8];
    int4 da = d4[idx], db = d4[idx + n8];
    g_srcsorted[atomicAdd(&g_cursor[da.x], 1)] = sa.x;
    g_srcsorted[atomicAdd(&g_cursor[da.y], 1)] = sa.y;
    g_srcsorted[atomicAdd(&g_cursor[da.z], 1)] = sa.z;
    g_srcsorted[atomicAdd(&g_cursor[da.w], 1)] = sa.w;
    g_srcsorted[atomicAdd(&g_cursor[db.x], 1)] = sb.x;
    g_srcsorted[atomicAdd(&g_cursor[db.y], 1)] = sb.y;
    g_srcsorted[atomicAdd(&g_cursor[db.z], 1)] = sb.z;
    g_srcsorted[atomicAdd(&g_cursor[db.w], 1)] = sb.w;
}

__global__ __launch_bounds__(256) void gather_kernel(const float* __restrict__ x) {
    int node = (blockIdx.x * blockDim.x + threadIdx.x) >> 5;
    int lane = threadIdx.x & 31;
    if (node >= N_NODES) return;
    int start = g_off[node];
    int deg = g_off[node + 1] - start;
    float4 acc = ((const float4*)(x + (size_t)node * NHID))[lane];
    const int* sl = g_srcsorted + start;
    int j = 0;
    for (; j + 4 <= deg; j += 4) {
        int s0 = sl[j], s1 = sl[j + 1], s2 = sl[j + 2], s3 = sl[j + 3];
        float4 v0 = ((const float4*)(x + (size_t)s0 * NHID))[lane];
        float4 v1 = ((const float4*)(x + (size_t)s1 * NHID))[lane];
        float4 v2 = ((const float4*)(x + (size_t)s2 * NHID))[lane];
        float4 v3 = ((const float4*)(x + (size_t)s3 * NHID))[lane];
        acc.x += v0.x + v1.x + v2.x + v3.x;
        acc.y += v0.y + v1.y + v2.y + v3.y;
        acc.z += v0.z + v1.z + v2.z + v3.z;
        acc.w += v0.w + v1.w + v2.w + v3.w;
    }
    for (; j < deg; j++) {
        int s0 = sl[j];
        float4 v0 = ((const float4*)(x + (size_t)s0 * NHID))[lane];
        acc.x += v0.x; acc.y += v0.y; acc.z += v0.z; acc.w += v0.w;
    }
    // write fragment-major
    int tile = node >> 7, r = node & 127;
    int rb = r >> 4, rr = r & 15;
    int s0 = 2 * lane, ks = s0 >> 3, s8 = s0 & 7;
    int p = ((rr >= 8) ? 1 : 0) + ((s8 >= 4) ? 2 : 0);
    int fl = (rr & 7) * 4 + (s8 & 3);
    int i0 = rb * 1024 + ks * 128 + fl * 4 + p;
    uint4 q = split4i(acc);
    uint2* o = (uint2*)(g_Af + (size_t)tile * 65536);
    o[i0] = make_uint2(q.x, q.y);
    o[i0 + 4] = make_uint2(q.z, q.w);
}

__global__ __launch_bounds__(128) void w2prep_kernel(
    const float* __restrict__ gamma, const float* __restrict__ beta,
    const float* __restrict__ W2, const float* __restrict__ b2) {
    __shared__ float sA[NHID], sB[NHID];
    int t = threadIdx.x;
    float mean = g_sum[t] * (1.f / N_NODES);
    float var = g_sumsq[t] * (1.f / N_NODES) - mean * mean;
    float a = gamma[t] * rsqrtf(var + BN_EPS);
    sA[t] = a;
    sB[t] = beta[t] - mean * a;
    __syncthreads();
    float c = b2[t];
    const float4* wr = (const float4*)(W2 + t * NHID);
    uint2* o = (uint2*)g_W2f;
    int cb = t >> 3, cc = t & 7;
#pragma unroll 8
    for (int k4 = 0; k4 < 32; k4++) {
        float4 w = wr[k4];
        int k = k4 * 4;
        c += w.x * sB[k] + w.y * sB[k + 1] + w.z * sB[k + 2] + w.w * sB[k + 3];
        w.x *= sA[k]; w.y *= sA[k + 1]; w.z *= sA[k + 2]; w.w *= sA[k + 3];
        uint4 q = split4i(w);
        int s0 = 2 * k4, ks = s0 >> 3, s8 = s0 & 7;
        int p = (s8 >= 4) ? 1 : 0;
        int fl = cc * 4 + (s8 & 3);
        int i0 = cb * 512 + ks * 64 + fl * 2 + p;
        o[i0] = make_uint2(q.x, q.y);
        o[i0 + 2] = make_uint2(q.z, q.w);
    }
    g_c2[t] = c;
}

// ---------------- HMMA GEMM: fragment-major global operands -------------------
// 256 thr = 8 warps, warp-tile m32 x n64. No smem in mainloop; smem (ht) only
// for epilogue transpose -> 3 CTAs/SM, 391 blocks = 1 wave.
#define GSM_BYTES (128 * 132 * 4 + 256)

template <bool FIRST>
__global__ __launch_bounds__(256) void mma_kernel(
    const uint4* __restrict__ Af, const uint4* __restrict__ Wf,
    const float* __restrict__ bias,
    unsigned char* __restrict__ outHf, float* __restrict__ outF) {
    extern __shared__ unsigned char sm[];
    const u32 smb = smem_u32(sm);
    float* ht = (float*)sm;           // 128 x 132 fp32

    const int tid = threadIdx.x;
    const int wid = tid >> 5;
    const int lane = tid & 31;
    const int g = lane >> 2;
    const int tig = lane & 3;
    const int r0 = (wid >> 1) * 32;
    const int nbase = (wid & 1) * 64;
    const int bidx = blockIdx.x;
    const int rows = min(128, N_NODES - bidx * 128);

    const uint4* At = Af + (size_t)bidx * 4096;   // 4096 uint4 per tile

    float acc[2][8][4];
#pragma unroll
    for (int rs = 0; rs < 2; rs++)
#pragma unroll
        for (int nb = 0; nb < 8; nb++)
#pragma unroll
            for (int q = 0; q < 4; q++) acc[rs][nb][q] = 0.f;

#pragma unroll
    for (int ks = 0; ks < 8; ks++) {
        uint4 qa[2][2];
#pragma unroll
        for (int rs = 0; rs < 2; rs++) {
            int u4 = ((wid >> 1) * 2 + rs) * 512 + ks * 64 + lane * 2;
            qa[rs][0] = At[u4];
            qa[rs][1] = At[u4 + 1];
        }
#pragma unroll
        for (int nb = 0; nb < 8; nb++) {
            uint4 qb = Wf[((wid & 1) * 8 + nb) * 256 + ks * 32 + lane];
#pragma unroll
            for (int rs = 0; rs < 2; rs++) {
                mma16816(acc[rs][nb], qa[rs][0].x, qa[rs][0].z, qa[rs][1].x, qa[rs][1].z, qb.x, qb.z);
                mma16816(acc[rs][nb], qa[rs][0].x, qa[rs][0].z, qa[rs][1].x, qa[rs][1].z, qb.y, qb.w);
                mma16816(acc[rs][nb], qa[rs][0].y, qa[rs][0].w, qa[rs][1].y, qa[rs][1].w, qb.x, qb.z);
            }
        }
    }

    // ---- fragments -> ht (bias, relu, row mask); no barrier needed before ----
#pragma unroll
    for (int rs = 0; rs < 2; rs++) {
#pragma unroll
        for (int nb = 0; nb < 8; nb++) {
            int row = r0 + rs * 16 + g;
            int col = nbase + nb * 8 + 2 * tig;
            float bc0 = bias[col], bc1 = bias[col + 1];
            float v0 = acc[rs][nb][0] + bc0, v1 = acc[rs][nb][1] + bc1;
            float v2 = acc[rs][nb][2] + bc0, v3 = acc[rs][nb][3] + bc1;
            if (FIRST) {
                v0 = fmaxf(v0, 0.f); v1 = fmaxf(v1, 0.f);
                v2 = fmaxf(v2, 0.f); v3 = fmaxf(v3, 0.f);
            }
            if (row >= rows) { v0 = 0.f; v1 = 0.f; }
            if (row + 8 >= rows) { v2 = 0.f; v3 = 0.f; }
            sts2f(smb + (row * 132 + col) * 4, v0, v1);
            sts2f(smb + ((row + 8) * 132 + col) * 4, v2, v3);
        }
    }
    __syncthreads();

    // ---- epilogue ----
    if (FIRST) {
        if (tid < 128) {
            float s1 = 0.f, s2 = 0.f;
#pragma unroll 8
            for (int r = 0; r < 128; r++) {
                float v = ht[r * 132 + tid];
                s1 += v;
                s2 += v * v;
            }
            atomicAdd(&g_sum[tid], s1);
            atomicAdd(&g_sumsq[tid], s2);
        }
        uint2* oh = (uint2*)(outHf + (size_t)bidx * 65536);
        for (int i = tid; i < 4096; i += 256) {
            int row = i >> 5, c4 = i & 31;
            float4 v = *(float4*)&ht[row * 132 + c4 * 4];
            uint4 q = split4i(v);
            int rb = row >> 4, rr = row & 15;
            int s0 = 2 * c4, ks = s0 >> 3, s8 = s0 & 7;
            int p = ((rr >= 8) ? 1 : 0) + ((s8 >= 4) ? 2 : 0);
            int fl = (rr & 7) * 4 + (s8 & 3);
            int i0 = rb * 1024 + ks * 128 + fl * 4 + p;
            oh[i0] = make_uint2(q.x, q.y);
            oh[i0 + 4] = make_uint2(q.z, q.w);
        }
    } else {
        for (int i = tid; i < 4096; i += 256) {
            int row = i >> 5, c4 = i & 31;
            if (row < rows) {
                float4 v = *(float4*)&ht[row * 132 + c4 * 4];
                ((float4*)(outF + (size_t)(bidx * 128 + row) * NHID))[c4] = v;
            }
        }
    }
}

// ---------------- launch ------------------------------------------------------
extern "C" void kernel_launch(void* const* d_in, const int* in_sizes, int n_in,
                              void* d_out, int out_size) {
    const float* x     = (const float*)d_in[0];
    const int*   ei    = (const int*)d_in[1];
    const float* W1    = (const float*)d_in[2];
    const float* b1    = (const float*)d_in[3];
    const float* gamma = (const float*)d_in[4];
    const float* beta  = (const float*)d_in[5];
    const float* W2    = (const float*)d_in[6];
    const float* b2    = (const float*)d_in[7];
    float* out = (float*)d_out;

    unsigned char *af, *hf, *w1f, *w2f;
    float* c2p;
    cudaGetSymbolAddress((void**)&af, g_Af);
    cudaGetSymbolAddress((void**)&hf, g_Hf);
    cudaGetSymbolAddress((void**)&w1f, g_W1f);
    cudaGetSymbolAddress((void**)&w2f, g_W2f);
    cudaGetSymbolAddress((void**)&c2p, g_c2);

    cudaFuncSetAttribute(mma_kernel<true>,
                         cudaFuncAttributeMaxDynamicSharedMemorySize, GSM_BYTES);
    cudaFuncSetAttribute(mma_kernel<false>,
                         cudaFuncAttributeMaxDynamicSharedMemorySize, GSM_BYTES);

    const int e8blocks = (N_EDGES / 8 + 255) / 256;
    hist_kernel<<<e8blocks, 256>>>(ei);
    partial_kernel<<<NBLK, 256>>>();
    offsets_kernel<<<NBLK + 1, 256>>>(W1);
    reorder_kernel<<<e8blocks, 256>>>(ei);
    gather_kernel<<<(N_NODES + 7) / 8, 256>>>(x);

    mma_kernel<true><<<NTILE, 256, GSM_BYTES>>>(
        (const uint4*)af, (const uint4*)w1f, b1, hf, nullptr);
    w2prep_kernel<<<1, 128>>>(gamma, beta, W2, b2);
    mma_kernel<false><<<NTILE, 256, GSM_BYTES>>>(
        (const uint4*)hf, (const uint4*)w2f, c2p, nullptr, out);
}

// round 13
// speedup vs baseline: 1.3942x; 1.3942x over previous
#include <cuda_runtime.h>
#include <cuda_bf16.h>

#define N_NODES 50000
#define N_EDGES 800000
#define NHID 128
#define BN_EPS 1e-5f
#define NBLK 196                 // ceil(50000/256)
#define NTILE 391                // ceil(50000/128)
#define MMA_GRID 148

typedef unsigned long long u64;
typedef unsigned int u32;

// ---------------- helpers ----------------------------------------------------
__device__ __forceinline__ u32 smem_u32(const void* p) {
    u32 a;
    asm("{ .reg .u64 t; cvta.to.shared.u64 t, %1; cvt.u32.u64 %0, t; }"
        : "=r"(a) : "l"(p));
    return a;
}
__device__ __forceinline__ void lds2(u32 addr, u32& a, u32& b) {
    asm volatile("ld.shared.v2.u32 {%0, %1}, [%2];" : "=r"(a), "=r"(b) : "r"(addr));
}
__device__ __forceinline__ void sts2f(u32 addr, float a, float b) {
    asm volatile("st.shared.v2.f32 [%0], {%1, %2};" :: "r"(addr), "f"(a), "f"(b) : "memory");
}
__device__ __forceinline__ void cp16(u32 saddr, const void* gptr) {
    asm volatile("cp.async.cg.shared.global [%0], [%1], 16;"
                 :: "r"(saddr), "l"(gptr) : "memory");
}
#define CP_COMMIT() asm volatile("cp.async.commit_group;" ::: "memory")
#define CP_WAIT0()  asm volatile("cp.async.wait_group 0;" ::: "memory")

__device__ __forceinline__ void mma16816(float* c, u32 a0, u32 a1, u32 a2, u32 a3,
                                         u32 b0, u32 b1) {
    asm volatile(
        "mma.sync.aligned.m16n8k16.row.col.f32.bf16.bf16.f32 "
        "{%0,%1,%2,%3}, {%4,%5,%6,%7}, {%8,%9}, {%0,%1,%2,%3};"
        : "+f"(c[0]), "+f"(c[1]), "+f"(c[2]), "+f"(c[3])
        : "r"(a0), "r"(a1), "r"(a2), "r"(a3), "r"(b0), "r"(b1));
}
// split float4 -> interleaved uint4 {hi01, lo01, hi23, lo23} (bf16x2 words)
__device__ __forceinline__ uint4 split4i(float4 v) {
    __nv_bfloat162 h0 = __float22bfloat162_rn(make_float2(v.x, v.y));
    __nv_bfloat162 h1 = __float22bfloat162_rn(make_float2(v.z, v.w));
    float2 r0 = make_float2(v.x - __bfloat162float(h0.x), v.y - __bfloat162float(h0.y));
    float2 r1 = make_float2(v.z - __bfloat162float(h1.x), v.w - __bfloat162float(h1.y));
    __nv_bfloat162 l0 = __float22bfloat162_rn(r0);
    __nv_bfloat162 l1 = __float22bfloat162_rn(r1);
    uint4 q;
    q.x = *(u32*)&h0; q.y = *(u32*)&l0;
    q.z = *(u32*)&h1; q.w = *(u32*)&l1;
    return q;
}

// ---------------- scratch ----------------------------------------------------
__device__ float g_sum[NHID];
__device__ float g_sumsq[NHID];
__device__ float g_c2[NHID];
__device__ int   g_count[N_NODES];
__device__ int   g_off[N_NODES + 1];
__device__ int   g_cursor[N_NODES];
__device__ int   g_srcsorted[N_EDGES];
__device__ int   g_bsum[NBLK];
__device__ __align__(16) unsigned char g_Ahl[(size_t)NTILE * 65536];
__device__ __align__(16) unsigned char g_Hhl[(size_t)NTILE * 65536];
__device__ __align__(16) unsigned char g_W1hl[65536];
__device__ __align__(16) unsigned char g_W2hl[65536];

// ---------------- front-end kernels (R8, measured-good) -----------------------
__global__ __launch_bounds__(256) void hist_kernel(const int* __restrict__ ei) {
    const int n8 = N_EDGES / 8;
    int idx = blockIdx.x * blockDim.x + threadIdx.x;
    if (idx >= n8) return;
    const int4* d4 = (const int4*)(ei + N_EDGES);
    int4 a = d4[idx];
    int4 b = d4[idx + n8];
    atomicAdd(&g_count[a.x], 1); atomicAdd(&g_count[a.y], 1);
    atomicAdd(&g_count[a.z], 1); atomicAdd(&g_count[a.w], 1);
    atomicAdd(&g_count[b.x], 1); atomicAdd(&g_count[b.y], 1);
    atomicAdd(&g_count[b.z], 1); atomicAdd(&g_count[b.w], 1);
}

__global__ __launch_bounds__(256) void partial_kernel() {
    int t = threadIdx.x;
    int i = blockIdx.x * 256 + t;
    int v = (i < N_NODES) ? g_count[i] : 0;
#pragma unroll
    for (int o = 16; o > 0; o >>= 1) v += __shfl_down_sync(~0u, v, o);
    __shared__ int ws[8];
    if ((t & 31) == 0) ws[t >> 5] = v;
    __syncthreads();
    if (t == 0) {
        int s = 0;
#pragma unroll
        for (int k = 0; k < 8; k++) s += ws[k];
        g_bsum[blockIdx.x] = s;
    }
}

__global__ __launch_bounds__(256) void offsets_kernel(const float* __restrict__ W1) {
    int t = threadIdx.x;
    int bid = blockIdx.x;
    if (bid == NBLK) {           // W1 -> interleaved bf16 hi/lo
        if (t < 128) {
            const float4* wr = (const float4*)(W1 + t * NHID);
            uint4* dst = (uint4*)g_W1hl + t * 32;
#pragma unroll 8
            for (int k4 = 0; k4 < 32; k4++) dst[k4] = split4i(wr[k4]);
        }
        return;
    }
    __shared__ int sb[256];
    __shared__ int sh[256];
    sb[t] = (t < NBLK) ? g_bsum[t] : 0;
    __syncthreads();
#pragma unroll
    for (int o = 1; o < 256; o <<= 1) {
        int u = (t >= o) ? sb[t - o] : 0;
        __syncthreads();
        sb[t] += u;
        __syncthreads();
    }
    int base = (bid > 0) ? sb[bid - 1] : 0;

    int i = bid * 256 + t;
    int v = (i < N_NODES) ? g_count[i] : 0;
    sh[t] = v;
    __syncthreads();
#pragma unroll
    for (int o = 1; o < 256; o <<= 1) {
        int u = (t >= o) ? sh[t - o] : 0;
        __syncthreads();
        sh[t] += u;
        __syncthreads();
    }
    int off = base + sh[t] - v;
    if (i < N_NODES) {
        g_off[i] = off;
        g_cursor[i] = off;
        g_count[i] = 0;
    } else if (i == N_NODES) {
        g_off[N_NODES] = N_EDGES;
    }
    if (bid == 0 && t < NHID) { g_sum[t] = 0.f; g_sumsq[t] = 0.f; }
}

__global__ __launch_bounds__(256) void reorder_kernel(const int* __restrict__ ei) {
    const int n8 = N_EDGES / 8;
    int idx = blockIdx.x * blockDim.x + threadIdx.x;
    if (idx >= n8) return;
    const int4* s4 = (const int4*)ei;
    const int4* d4 = (const int4*)(ei + N_EDGES);
    int4 sa = s4[idx], sb = s4[idx + n8];
    int4 da = d4[idx], db = d4[idx + n8];
    g_srcsorted[atomicAdd(&g_cursor[da.x], 1)] = sa.x;
    g_srcsorted[atomicAdd(&g_cursor[da.y], 1)] = sa.y;
    g_srcsorted[atomicAdd(&g_cursor[da.z], 1)] = sa.z;
    g_srcsorted[atomicAdd(&g_cursor[da.w], 1)] = sa.w;
    g_srcsorted[atomicAdd(&g_cursor[db.x], 1)] = sb.x;
    g_srcsorted[atomicAdd(&g_cursor[db.y], 1)] = sb.y;
    g_srcsorted[atomicAdd(&g_cursor[db.z], 1)] = sb.z;
    g_srcsorted[atomicAdd(&g_cursor[db.w], 1)] = sb.w;
}

__global__ __launch_bounds__(256) void gather_kernel(const float* __restrict__ x) {
    int node = (blockIdx.x * blockDim.x + threadIdx.x) >> 5;
    int lane = threadIdx.x & 31;
    if (node >= N_NODES) return;
    int start = g_off[node];
    int deg = g_off[node + 1] - start;
    float4 acc = ((const float4*)(x + (size_t)node * NHID))[lane];
    const int* sl = g_srcsorted + start;
    int j = 0;
    for (; j + 4 <= deg; j += 4) {
        int s0 = sl[j], s1 = sl[j + 1], s2 = sl[j + 2], s3 = sl[j + 3];
        float4 v0 = ((const float4*)(x + (size_t)s0 * NHID))[lane];
        float4 v1 = ((const float4*)(x + (size_t)s1 * NHID))[lane];
        float4 v2 = ((const float4*)(x + (size_t)s2 * NHID))[lane];
        float4 v3 = ((const float4*)(x + (size_t)s3 * NHID))[lane];
        acc.x += v0.x + v1.x + v2.x + v3.x;
        acc.y += v0.y + v1.y + v2.y + v3.y;
        acc.z += v0.z + v1.z + v2.z + v3.z;
        acc.w += v0.w + v1.w + v2.w + v3.w;
    }
    for (; j < deg; j++) {
        int s0 = sl[j];
        float4 v0 = ((const float4*)(x + (size_t)s0 * NHID))[lane];
        acc.x += v0.x; acc.y += v0.y; acc.z += v0.z; acc.w += v0.w;
    }
    ((uint4*)g_Ahl)[(size_t)node * 32 + lane] = split4i(acc);
}

__global__ __launch_bounds__(128) void w2prep_kernel(
    const float* __restrict__ gamma, const float* __restrict__ beta,
    const float* __restrict__ W2, const float* __restrict__ b2) {
    __shared__ float sA[NHID], sB[NHID];
    int t = threadIdx.x;
    float mean = g_sum[t] * (1.f / N_NODES);
    float var = g_sumsq[t] * (1.f / N_NODES) - mean * mean;
    float a = gamma[t] * rsqrtf(var + BN_EPS);
    sA[t] = a;
    sB[t] = beta[t] - mean * a;
    __syncthreads();
    float c = b2[t];
    const float4* wr = (const float4*)(W2 + t * NHID);
    uint4* dst = (uint4*)g_W2hl + t * 32;
#pragma unroll 8
    for (int k4 = 0; k4 < 32; k4++) {
        float4 w = wr[k4];
        int k = k4 * 4;
        c += w.x * sB[k] + w.y * sB[k + 1] + w.z * sB[k + 2] + w.w * sB[k + 3];
        w.x *= sA[k]; w.y *= sA[k + 1]; w.z *= sA[k + 2]; w.w *= sA[k + 3];
        dst[k4] = split4i(w);
    }
    g_c2[t] = c;
}

// ---------------- persistent HMMA GEMM: W staged once, A double-buffered ------
// SMEM: [W 67584][A0 67584][A1 67584][bias 512]. ht overlays CURRENT A buffer.
#define SROW 66                       // u64 per row (64 + 2 pad)
#define TILE_SMEM 67584               // 128 rows * 528 B
#define GSM_BYTES (3 * TILE_SMEM + 512)

template <bool FIRST>
__global__ __launch_bounds__(256) void mma_kernel(
    const uint4* __restrict__ Ahl, const uint4* __restrict__ Whl,
    const float* __restrict__ bias,
    unsigned char* __restrict__ outHhl, float* __restrict__ outF) {
    extern __shared__ unsigned char sm[];
    const u32 smb = smem_u32(sm);
    const u32 bw = smb;                               // W tile
    float* biasS = (float*)(sm + 3 * TILE_SMEM);

    const int tid = threadIdx.x;
    const int wid = tid >> 5;
    const int lane = tid & 31;
    const int g = lane >> 2;
    const int tig = lane & 3;
    const int r0 = (wid >> 1) * 32;
    const int nbase = (wid & 1) * 64;
    const int bid = blockIdx.x;

    // ---- stage W (once) + prefetch first A tile, both via cp.async ----
#pragma unroll
    for (int it = 0; it < 16; it++) {
        int i = it * 256 + tid;
        cp16(bw + ((i >> 5) * 33 + (i & 31)) * 16, Whl + i);
    }
    {
        const uint4* gA = Ahl + (size_t)bid * 4096;
#pragma unroll
        for (int it = 0; it < 16; it++) {
            int i = it * 256 + tid;
            cp16(smb + TILE_SMEM + ((i >> 5) * 33 + (i & 31)) * 16, gA + i);
        }
    }
    CP_COMMIT();
    if (tid < 128) biasS[tid] = bias[tid];
    CP_WAIT0();
    __syncthreads();

    int cur = 0;
    for (int tile = bid; tile < NTILE; tile += MMA_GRID) {
        const u32 aw = smb + TILE_SMEM + cur * TILE_SMEM;
        float* ht = (float*)(sm + TILE_SMEM + cur * TILE_SMEM);
        const int rows = min(128, N_NODES - tile * 128);

        // prefetch next tile into other buffer (overlaps mainloop+epilogue)
        if (tile + MMA_GRID < NTILE) {
            const uint4* gA = Ahl + (size_t)(tile + MMA_GRID) * 4096;
            u32 dst = smb + TILE_SMEM + (1 - cur) * TILE_SMEM;
#pragma unroll
            for (int it = 0; it < 16; it++) {
                int i = it * 256 + tid;
                cp16(dst + ((i >> 5) * 33 + (i & 31)) * 16, gA + i);
            }
            CP_COMMIT();
        }

        // ---- mainloop ----
        float acc[2][8][4];
#pragma unroll
        for (int rs = 0; rs < 2; rs++)
#pragma unroll
            for (int nb = 0; nb < 8; nb++)
#pragma unroll
                for (int q = 0; q < 4; q++) acc[rs][nb][q] = 0.f;

        for (int ks = 0; ks < 8; ks++) {
            const int kb2 = ks * 8;
            u32 ah[2][4], al[2][4];
#pragma unroll
            for (int rs = 0; rs < 2; rs++) {
                int rb = r0 + rs * 16 + g;
                lds2(aw + (rb * SROW + tig + kb2) * 8,       ah[rs][0], al[rs][0]);
                lds2(aw + ((rb + 8) * SROW + tig + kb2) * 8, ah[rs][1], al[rs][1]);
                lds2(aw + (rb * SROW + tig + 4 + kb2) * 8,       ah[rs][2], al[rs][2]);
                lds2(aw + ((rb + 8) * SROW + tig + 4 + kb2) * 8, ah[rs][3], al[rs][3]);
            }
#pragma unroll
            for (int nb = 0; nb < 8; nb++) {
                int nn = nbase + nb * 8 + g;
                u32 b0h, b0l, b1h, b1l;
                lds2(bw + (nn * SROW + tig + kb2) * 8,     b0h, b0l);
                lds2(bw + (nn * SROW + tig + 4 + kb2) * 8, b1h, b1l);
#pragma unroll
                for (int rs = 0; rs < 2; rs++) {
                    mma16816(acc[rs][nb], ah[rs][0], ah[rs][1], ah[rs][2], ah[rs][3], b0h, b1h);
                    mma16816(acc[rs][nb], ah[rs][0], ah[rs][1], ah[rs][2], ah[rs][3], b0l, b1l);
                    mma16816(acc[rs][nb], al[rs][0], al[rs][1], al[rs][2], al[rs][3], b0h, b1h);
                }
            }
        }
        __syncthreads();   // all warps done reading A[cur]; reuse as ht

        // ---- fragments -> ht (bias, relu, row mask) ----
#pragma unroll
        for (int rs = 0; rs < 2; rs++) {
#pragma unroll
            for (int nb = 0; nb < 8; nb++) {
                int row = r0 + rs * 16 + g;
                int col = nbase + nb * 8 + 2 * tig;
                float bc0 = biasS[col], bc1 = biasS[col + 1];
                float v0 = acc[rs][nb][0] + bc0, v1 = acc[rs][nb][1] + bc1;
                float v2 = acc[rs][nb][2] + bc0, v3 = acc[rs][nb][3] + bc1;
                if (FIRST) {
                    v0 = fmaxf(v0, 0.f); v1 = fmaxf(v1, 0.f);
                    v2 = fmaxf(v2, 0.f); v3 = fmaxf(v3, 0.f);
                }
                if (row >= rows) { v0 = 0.f; v1 = 0.f; }
                if (row + 8 >= rows) { v2 = 0.f; v3 = 0.f; }
                u32 htb = smb + TILE_SMEM + cur * TILE_SMEM;
                sts2f(htb + (row * 132 + col) * 4, v0, v1);
                sts2f(htb + ((row + 8) * 132 + col) * 4, v2, v3);
            }
        }
        __syncthreads();

        // ---- epilogue ----
        if (FIRST) {
            if (tid < 128) {
                float s1 = 0.f, s2 = 0.f;
#pragma unroll 8
                for (int r = 0; r < 128; r++) {
                    float v = ht[r * 132 + tid];
                    s1 += v;
                    s2 += v * v;
                }
                atomicAdd(&g_sum[tid], s1);
                atomicAdd(&g_sumsq[tid], s2);
            }
            uint4* oh = (uint4*)(outHhl + (size_t)tile * 65536);
            for (int i = tid; i < 4096; i += 256) {
                int row = i >> 5, c4 = i & 31;
                float4 v = *(float4*)&ht[row * 132 + c4 * 4];
                oh[row * 32 + c4] = split4i(v);
            }
        } else {
            for (int i = tid; i < 4096; i += 256) {
                int row = i >> 5, c4 = i & 31;
                if (row < rows) {
                    float4 v = *(float4*)&ht[row * 132 + c4 * 4];
                    ((float4*)(outF + (size_t)(tile * 128 + row) * NHID))[c4] = v;
                }
            }
        }
        CP_WAIT0();        // next A buffer fully landed
        __syncthreads();
        cur ^= 1;
    }
}

// ---------------- launch ------------------------------------------------------
extern "C" void kernel_launch(void* const* d_in, const int* in_sizes, int n_in,
                              void* d_out, int out_size) {
    const float* x     = (const float*)d_in[0];
    const int*   ei    = (const int*)d_in[1];
    const float* W1    = (const float*)d_in[2];
    const float* b1    = (const float*)d_in[3];
    const float* gamma = (const float*)d_in[4];
    const float* beta  = (const float*)d_in[5];
    const float* W2    = (const float*)d_in[6];
    const float* b2    = (const float*)d_in[7];
    float* out = (float*)d_out;

    unsigned char *ahl, *hhl, *w1hl, *w2hl;
    float* c2p;
    cudaGetSymbolAddress((void**)&ahl, g_Ahl);
    cudaGetSymbolAddress((void**)&hhl, g_Hhl);
    cudaGetSymbolAddress((void**)&w1hl, g_W1hl);
    cudaGetSymbolAddress((void**)&w2hl, g_W2hl);
    cudaGetSymbolAddress((void**)&c2p, g_c2);

    cudaFuncSetAttribute(mma_kernel<true>,
                         cudaFuncAttributeMaxDynamicSharedMemorySize, GSM_BYTES);
    cudaFuncSetAttribute(mma_kernel<false>,
                         cudaFuncAttributeMaxDynamicSharedMemorySize, GSM_BYTES);

    const int e8blocks = (N_EDGES / 8 + 255) / 256;
    hist_kernel<<<e8blocks, 256>>>(ei);
    partial_kernel<<<NBLK, 256>>>();
    offsets_kernel<<<NBLK + 1, 256>>>(W1);
    reorder_kernel<<<e8blocks, 256>>>(ei);
    gather_kernel<<<(N_NODES + 7) / 8, 256>>>(x);

    mma_kernel<true><<<MMA_GRID, 256, GSM_BYTES>>>(
        (const uint4*)ahl, (const uint4*)w1hl, b1, hhl, nullptr);
    w2prep_kernel<<<1, 128>>>(gamma, beta, W2, b2);
    mma_kernel<false><<<MMA_GRID, 256, GSM_BYTES>>>(
        (const uint4*)hhl, (const uint4*)w2hl, c2p, nullptr, out);
}